// round 2
// baseline (speedup 1.0000x reference)
#include <cuda_runtime.h>
#include <math.h>

namespace {
constexpr int KCODES = 1024;
constexpr int D      = 64;
constexpr int BATCH  = 32;
constexpr int HWSZ   = 64 * 64;          // 4096
constexpr int NTOK   = BATCH * HWSZ;     // 131072
constexpr int CHUNK  = 128;              // codes per smem tile (32 KB)
constexpr int TPB    = 256;
constexpr float MARGIN = 1e-4f;          // rescue threshold (>> grid ulp 7.6e-6)
}

__device__ float g_cnorm[KCODES];
__device__ int   g_counts[KCODES];

// Kernel A: per-code squared norms + zero usage histogram (every launch -> graph-replay safe).
__global__ void vq_prep(const float* __restrict__ codebook) {
    int k = blockIdx.x * blockDim.x + threadIdx.x;
    if (k < KCODES) {
        const float4* c = reinterpret_cast<const float4*>(codebook + k * D);
        float s = 0.f;
#pragma unroll
        for (int i = 0; i < D / 4; ++i) {
            float4 v = c[i];
            s = fmaf(v.x, v.x, s);
            s = fmaf(v.y, v.y, s);
            s = fmaf(v.z, v.z, s);
            s = fmaf(v.w, v.w, s);
        }
        g_cnorm[k] = s;
        g_counts[k] = 0;
    }
}

// Exact emulation of the reference's rounded score for one code:
//   d32 = fl32( fl32( A32 - 2*fl32(dot) ) + fl32(C) )
// dot/C accumulated in fp64 (effectively exact); A32 passed in.
__device__ __forceinline__ float ref_score(const float* __restrict__ cb, int k,
                                           const float* x, float A32) {
    const float* cp = cb + k * D;
    double dot = 0.0, C = 0.0;
#pragma unroll
    for (int i = 0; i < D; ++i) {
        float cv = cp[i];
        dot += (double)x[i] * (double)cv;
        C   += (double)(cv * cv);          // ref squares in fp32, then sums
    }
    float t1 = (float)dot;                 // matmul output rounding
    float t2 = A32 - 2.0f * t1;            // 2*t1 exact; one rounding
    float t3 = t2 + (float)C;              // final rounding -> the grid
    return t3;
}

// Kernel B: per-token argmin (top-2 tracked) + rare exact-rounding rescue
// + gather + straight-through output.
__global__ __launch_bounds__(TPB) void vq_main(const float* __restrict__ inputs,
                                               const float* __restrict__ codebook,
                                               float* __restrict__ out) {
    __shared__ float sc[CHUNK * D];   // 32 KB code tile
    __shared__ float sn[CHUNK];       // code norms

    const int tid = threadIdx.x;
    const int tok = blockIdx.x * TPB + tid;
    const int b   = tok >> 12;
    const int hw  = tok & (HWSZ - 1);
    const float* xin = inputs + (b * D) * HWSZ + hw;   // NCHW: channel stride = HW

    float x[D];
#pragma unroll
    for (int c = 0; c < D; ++c) x[c] = xin[c * HWSZ];  // coalesced across threads

    float best  = 3.4e38f, best2 = 3.4e38f;
    int   bestk = 0,       bestk2 = 0;

    for (int k0 = 0; k0 < KCODES; k0 += CHUNK) {
        __syncthreads();
        {
            const float4* src = reinterpret_cast<const float4*>(codebook + k0 * D);
            float4*       dst = reinterpret_cast<float4*>(sc);
#pragma unroll
            for (int i = tid; i < CHUNK * D / 4; i += TPB) dst[i] = src[i];
            if (tid < CHUNK) sn[tid] = g_cnorm[k0 + tid];
        }
        __syncthreads();

        for (int kk = 0; kk < CHUNK; ++kk) {
            const float4* cp4 = reinterpret_cast<const float4*>(sc + kk * D);
            float d0 = 0.f, d1 = 0.f, d2 = 0.f, d3 = 0.f;
#pragma unroll
            for (int i = 0; i < D / 4; ++i) {
                float4 cv = cp4[i];   // LDS.128 warp-broadcast
                d0 = fmaf(x[4 * i + 0], cv.x, d0);
                d1 = fmaf(x[4 * i + 1], cv.y, d1);
                d2 = fmaf(x[4 * i + 2], cv.z, d2);
                d3 = fmaf(x[4 * i + 3], cv.w, d3);
            }
            float s = sn[kk] - 2.0f * ((d0 + d1) + (d2 + d3));
            if (s < best)       { best2 = best; bestk2 = bestk; best = s; bestk = k0 + kk; }
            else if (s < best2) { best2 = s; bestk2 = k0 + kk; }
        }
    }

    // Rare rescue path: near-tie -> emulate the reference's fp32 rounding exactly,
    // including its lowest-index tie-break on equal rounded scores.
    if (best2 - best < MARGIN) {
        double A = 0.0;
#pragma unroll
        for (int i = 0; i < D; ++i) A += (double)(x[i] * x[i]);  // fp32 squares, exact sum
        float A32 = (float)A;
        int klo = min(bestk, bestk2), khi = max(bestk, bestk2);
        float dlo = ref_score(codebook, klo, x, A32);
        float dhi = ref_score(codebook, khi, x, A32);
        bestk = (dhi < dlo) ? khi : klo;   // ties -> lower index, matching argmin
    }

    atomicAdd(&g_counts[bestk], 1);

    const float4* q = reinterpret_cast<const float4*>(codebook + bestk * D);
    float* outp = out + (b * D) * HWSZ + hw;
#pragma unroll
    for (int i = 0; i < D / 4; ++i) {
        float4 qv = __ldg(&q[i]);
        int c = i * 4;
        outp[(c + 0) * HWSZ] = x[c + 0] + (qv.x - x[c + 0]);
        outp[(c + 1) * HWSZ] = x[c + 1] + (qv.y - x[c + 1]);
        outp[(c + 2) * HWSZ] = x[c + 2] + (qv.z - x[c + 2]);
        outp[(c + 3) * HWSZ] = x[c + 3] + (qv.w - x[c + 3]);
    }
}

// Kernel C: perplexity = exp(-sum(e * log(e + 1e-10))), e = counts / N.
__global__ void vq_perplexity(float* __restrict__ out, int out_size) {
    const int k = threadIdx.x;
    float e = (float)g_counts[k] * (1.0f / (float)NTOK);
    float v = e * logf(e + 1e-10f);
#pragma unroll
    for (int o = 16; o > 0; o >>= 1) v += __shfl_down_sync(0xffffffffu, v, o);
    __shared__ float red[32];
    if ((k & 31) == 0) red[k >> 5] = v;
    __syncthreads();
    if (k < 32) {
        float s = red[k];
#pragma unroll
        for (int o = 16; o > 0; o >>= 1) s += __shfl_down_sync(0xffffffffu, s, o);
        if (k == 0 && out_size > NTOK * D) out[NTOK * D] = expf(-s);
    }
}

extern "C" void kernel_launch(void* const* d_in, const int* in_sizes, int n_in,
                              void* d_out, int out_size) {
    const float* inputs   = (const float*)d_in[0];
    const float* codebook = (const float*)d_in[1];
    float*       out      = (float*)d_out;

    vq_prep<<<(KCODES + 255) / 256, 256>>>(codebook);
    vq_main<<<NTOK / TPB, TPB>>>(inputs, codebook, out);
    vq_perplexity<<<1, KCODES>>>(out, out_size);
}

// round 3
// speedup vs baseline: 1.2310x; 1.2310x over previous
#include <cuda_runtime.h>
#include <math.h>

namespace {
constexpr int KCODES = 1024;
constexpr int D      = 64;
constexpr int BATCH  = 32;
constexpr int HWSZ   = 64 * 64;          // 4096
constexpr int NTOK   = BATCH * HWSZ;     // 131072
constexpr int CHUNK  = 128;              // codes per smem tile (32 KB)
constexpr int TPB    = 256;
constexpr float MARGIN = 1e-4f;          // rescue threshold (>> score-grid ulp 7.6e-6)
}

__device__ float g_cnorm[KCODES];
__device__ int   g_counts[KCODES];

// ---- packed fp32x2 helpers (sm_103a FFMA2 path) ----
#define FMA2(d, a, b, c) \
    asm("fma.rn.f32x2 %0, %1, %2, %3;" : "=l"(d) : "l"(a), "l"(b), "l"(c))
#define ADD2(d, a, b) \
    asm("add.rn.f32x2 %0, %1, %2;" : "=l"(d) : "l"(a), "l"(b))

__device__ __forceinline__ unsigned long long pack2(float lo, float hi) {
    unsigned long long r;
    asm("mov.b64 %0, {%1, %2};" : "=l"(r) : "f"(lo), "f"(hi));
    return r;
}
__device__ __forceinline__ void unpack2(unsigned long long v, float& lo, float& hi) {
    asm("mov.b64 {%0, %1}, %2;" : "=f"(lo), "=f"(hi) : "l"(v));
}

// Kernel A: per-code squared norms + zero usage histogram (every launch -> graph-replay safe).
__global__ void vq_prep(const float* __restrict__ codebook) {
    int k = blockIdx.x * blockDim.x + threadIdx.x;
    if (k < KCODES) {
        const float4* c = reinterpret_cast<const float4*>(codebook + k * D);
        float s = 0.f;
#pragma unroll
        for (int i = 0; i < D / 4; ++i) {
            float4 v = c[i];
            s = fmaf(v.x, v.x, s);
            s = fmaf(v.y, v.y, s);
            s = fmaf(v.z, v.z, s);
            s = fmaf(v.w, v.w, s);
        }
        g_cnorm[k] = s;
        g_counts[k] = 0;
    }
}

// Exact emulation of the reference's rounded score for one code:
//   d32 = fl32( fl32( A32 - 2*fl32(dot) ) + fl32(C) )
__device__ __forceinline__ float ref_score(const float* __restrict__ cb, int k,
                                           const float* x, float A32) {
    const float* cp = cb + k * D;
    double dot = 0.0, C = 0.0;
#pragma unroll
    for (int i = 0; i < D; ++i) {
        float cv = cp[i];
        dot += (double)x[i] * (double)cv;
        C   += (double)(cv * cv);          // ref squares in fp32, then sums
    }
    float t1 = (float)dot;
    float t2 = A32 - 2.0f * t1;
    float t3 = t2 + (float)C;
    return t3;
}

// Kernel B: per-token argmin via packed f32x2 FMAs (top-2 tracked) + rare exact rescue
// + gather + straight-through output.
__global__ __launch_bounds__(TPB) void vq_main(const float* __restrict__ inputs,
                                               const float* __restrict__ codebook,
                                               float* __restrict__ out) {
    __shared__ float sc[CHUNK * D];   // 32 KB tile holding (-2 * code) values
    __shared__ float sn[CHUNK];       // code norms

    const int tid = threadIdx.x;
    const int tok = blockIdx.x * TPB + tid;
    const int b   = tok >> 12;
    const int hw  = tok & (HWSZ - 1);
    const float* xin = inputs + (b * D) * HWSZ + hw;   // NCHW: channel stride = HW

    float x[D];
#pragma unroll
    for (int c = 0; c < D; ++c) x[c] = xin[c * HWSZ];  // coalesced across threads

    unsigned long long x2[D / 2];
#pragma unroll
    for (int i = 0; i < D / 2; ++i) x2[i] = pack2(x[2 * i], x[2 * i + 1]);

    float best  = 3.4e38f, best2 = 3.4e38f;
    int   bestk = 0,       bestk2 = 0;

    for (int k0 = 0; k0 < KCODES; k0 += CHUNK) {
        __syncthreads();
        {
            // Stage -2*c (exact power-of-2 scale) so score = sn + sum(x * (-2c)).
            const float4* src = reinterpret_cast<const float4*>(codebook + k0 * D);
            float4*       dst = reinterpret_cast<float4*>(sc);
#pragma unroll
            for (int i = tid; i < CHUNK * D / 4; i += TPB) {
                float4 v = src[i];
                v.x *= -2.0f; v.y *= -2.0f; v.z *= -2.0f; v.w *= -2.0f;
                dst[i] = v;
            }
            if (tid < CHUNK) sn[tid] = g_cnorm[k0 + tid];
        }
        __syncthreads();

        for (int kk = 0; kk < CHUNK; ++kk) {
            const ulonglong2* cp = reinterpret_cast<const ulonglong2*>(sc + kk * D);
            unsigned long long a0 = pack2(sn[kk], 0.0f);  // fold ||c||^2 into lane 0
            unsigned long long a1 = 0ull, a2 = 0ull, a3 = 0ull;
#pragma unroll
            for (int i = 0; i < 8; ++i) {                 // 8 x (2 LDS.128 -> 4 FFMA2)
                ulonglong2 cv0 = cp[2 * i];
                ulonglong2 cv1 = cp[2 * i + 1];
                FMA2(a0, x2[4 * i + 0], cv0.x, a0);
                FMA2(a1, x2[4 * i + 1], cv0.y, a1);
                FMA2(a2, x2[4 * i + 2], cv1.x, a2);
                FMA2(a3, x2[4 * i + 3], cv1.y, a3);
            }
            unsigned long long s01, s23, sall;
            ADD2(s01, a0, a1);
            ADD2(s23, a2, a3);
            ADD2(sall, s01, s23);
            float lo, hi;
            unpack2(sall, lo, hi);
            float s = lo + hi;     // = ||c||^2 - 2*x.c
            if (s < best)       { best2 = best; bestk2 = bestk; best = s; bestk = k0 + kk; }
            else if (s < best2) { best2 = s; bestk2 = k0 + kk; }
        }
    }

    // Rare rescue: near-tie -> reproduce the reference's fp32 rounding exactly,
    // including its lowest-index tie-break.
    if (best2 - best < MARGIN) {
        double A = 0.0;
#pragma unroll
        for (int i = 0; i < D; ++i) A += (double)(x[i] * x[i]);
        float A32 = (float)A;
        int klo = min(bestk, bestk2), khi = max(bestk, bestk2);
        float dlo = ref_score(codebook, klo, x, A32);
        float dhi = ref_score(codebook, khi, x, A32);
        bestk = (dhi < dlo) ? khi : klo;
    }

    atomicAdd(&g_counts[bestk], 1);

    const float4* q = reinterpret_cast<const float4*>(codebook + bestk * D);
    float* outp = out + (b * D) * HWSZ + hw;
#pragma unroll
    for (int i = 0; i < D / 4; ++i) {
        float4 qv = __ldg(&q[i]);
        int c = i * 4;
        outp[(c + 0) * HWSZ] = x[c + 0] + (qv.x - x[c + 0]);
        outp[(c + 1) * HWSZ] = x[c + 1] + (qv.y - x[c + 1]);
        outp[(c + 2) * HWSZ] = x[c + 2] + (qv.z - x[c + 2]);
        outp[(c + 3) * HWSZ] = x[c + 3] + (qv.w - x[c + 3]);
    }
}

// Kernel C: perplexity = exp(-sum(e * log(e + 1e-10))), e = counts / N.
__global__ void vq_perplexity(float* __restrict__ out, int out_size) {
    const int k = threadIdx.x;
    float e = (float)g_counts[k] * (1.0f / (float)NTOK);
    float v = e * logf(e + 1e-10f);
#pragma unroll
    for (int o = 16; o > 0; o >>= 1) v += __shfl_down_sync(0xffffffffu, v, o);
    __shared__ float red[32];
    if ((k & 31) == 0) red[k >> 5] = v;
    __syncthreads();
    if (k < 32) {
        float s = red[k];
#pragma unroll
        for (int o = 16; o > 0; o >>= 1) s += __shfl_down_sync(0xffffffffu, s, o);
        if (k == 0 && out_size > NTOK * D) out[NTOK * D] = expf(-s);
    }
}

extern "C" void kernel_launch(void* const* d_in, const int* in_sizes, int n_in,
                              void* d_out, int out_size) {
    const float* inputs   = (const float*)d_in[0];
    const float* codebook = (const float*)d_in[1];
    float*       out      = (float*)d_out;

    vq_prep<<<(KCODES + 255) / 256, 256>>>(codebook);
    vq_main<<<NTOK / TPB, TPB>>>(inputs, codebook, out);
    vq_perplexity<<<1, KCODES>>>(out, out_size);
}

// round 4
// speedup vs baseline: 1.2335x; 1.0020x over previous
#include <cuda_runtime.h>
#include <math.h>

namespace {
constexpr int KCODES = 1024;
constexpr int D      = 64;
constexpr int BATCH  = 32;
constexpr int HWSZ   = 64 * 64;          // 4096
constexpr int NTOK   = BATCH * HWSZ;     // 131072
constexpr int CHUNK  = 128;              // codes per smem tile (32 KB)
constexpr int TPB    = 256;
constexpr float MARGIN = 1e-4f;          // rescue threshold (>> score-grid ulp 7.6e-6)
}

__device__ float g_cnorm[KCODES];
__device__ int   g_counts[KCODES];

// ---- packed fp32x2 helpers (sm_103a FFMA2 path) ----
#define FMA2(d, a, b, c) \
    asm("fma.rn.f32x2 %0, %1, %2, %3;" : "=l"(d) : "l"(a), "l"(b), "l"(c))
#define ADD2(d, a, b) \
    asm("add.rn.f32x2 %0, %1, %2;" : "=l"(d) : "l"(a), "l"(b))

__device__ __forceinline__ unsigned long long pack2(float lo, float hi) {
    unsigned long long r;
    asm("mov.b64 %0, {%1, %2};" : "=l"(r) : "f"(lo), "f"(hi));
    return r;
}
__device__ __forceinline__ void unpack2(unsigned long long v, float& lo, float& hi) {
    asm("mov.b64 {%0, %1}, %2;" : "=f"(lo), "=f"(hi) : "l"(v));
}

// Kernel A: per-code squared norms + zero usage histogram (every launch -> graph-replay safe).
__global__ void vq_prep(const float* __restrict__ codebook) {
    int k = blockIdx.x * blockDim.x + threadIdx.x;
    if (k < KCODES) {
        const float4* c = reinterpret_cast<const float4*>(codebook + k * D);
        float s = 0.f;
#pragma unroll
        for (int i = 0; i < D / 4; ++i) {
            float4 v = c[i];
            s = fmaf(v.x, v.x, s);
            s = fmaf(v.y, v.y, s);
            s = fmaf(v.z, v.z, s);
            s = fmaf(v.w, v.w, s);
        }
        g_cnorm[k] = s;
        g_counts[k] = 0;
    }
}

// Exact emulation of the reference's rounded score for one code:
//   d32 = fl32( fl32( A32 - 2*fl32(dot) ) + fl32(C) )
__device__ __forceinline__ float ref_score(const float* __restrict__ cb, int k,
                                           const float* x, float A32) {
    const float* cp = cb + k * D;
    double dot = 0.0, C = 0.0;
#pragma unroll
    for (int i = 0; i < D; ++i) {
        float cv = cp[i];
        dot += (double)x[i] * (double)cv;
        C   += (double)(cv * cv);          // ref squares in fp32, then sums
    }
    float t1 = (float)dot;
    float t2 = A32 - 2.0f * t1;
    float t3 = t2 + (float)C;
    return t3;
}

// Kernel B: per-token argmin via packed f32x2 FMAs (top-2 tracked) + rare exact rescue
// + gather + straight-through output.
__global__ __launch_bounds__(TPB) void vq_main(const float* __restrict__ inputs,
                                               const float* __restrict__ codebook,
                                               float* __restrict__ out) {
    __shared__ float sc[CHUNK * D];   // 32 KB tile holding (-2 * code) values
    __shared__ float sn[CHUNK];       // code norms

    const int tid = threadIdx.x;
    const int tok = blockIdx.x * TPB + tid;
    const int b   = tok >> 12;
    const int hw  = tok & (HWSZ - 1);
    const float* xin = inputs + (b * D) * HWSZ + hw;   // NCHW: channel stride = HW

    float x[D];
#pragma unroll
    for (int c = 0; c < D; ++c) x[c] = xin[c * HWSZ];  // coalesced across threads

    unsigned long long x2[D / 2];
#pragma unroll
    for (int i = 0; i < D / 2; ++i) x2[i] = pack2(x[2 * i], x[2 * i + 1]);

    float best  = 3.4e38f, best2 = 3.4e38f;
    int   bestk = 0,       bestk2 = 0;

    for (int k0 = 0; k0 < KCODES; k0 += CHUNK) {
        __syncthreads();
        {
            // Stage -2*c (exact power-of-2 scale) so score = sn + sum(x * (-2c)).
            const float4* src = reinterpret_cast<const float4*>(codebook + k0 * D);
            float4*       dst = reinterpret_cast<float4*>(sc);
#pragma unroll
            for (int i = tid; i < CHUNK * D / 4; i += TPB) {
                float4 v = src[i];
                v.x *= -2.0f; v.y *= -2.0f; v.z *= -2.0f; v.w *= -2.0f;
                dst[i] = v;
            }
            if (tid < CHUNK) sn[tid] = g_cnorm[k0 + tid];
        }
        __syncthreads();

        for (int kk = 0; kk < CHUNK; ++kk) {
            const ulonglong2* cp = reinterpret_cast<const ulonglong2*>(sc + kk * D);
            unsigned long long a0 = pack2(sn[kk], 0.0f);  // fold ||c||^2 into lane 0
            unsigned long long a1 = 0ull, a2 = 0ull, a3 = 0ull;
#pragma unroll
            for (int i = 0; i < 8; ++i) {                 // 8 x (2 LDS.128 -> 4 FFMA2)
                ulonglong2 cv0 = cp[2 * i];
                ulonglong2 cv1 = cp[2 * i + 1];
                FMA2(a0, x2[4 * i + 0], cv0.x, a0);
                FMA2(a1, x2[4 * i + 1], cv0.y, a1);
                FMA2(a2, x2[4 * i + 2], cv1.x, a2);
                FMA2(a3, x2[4 * i + 3], cv1.y, a3);
            }
            unsigned long long s01, s23, sall;
            ADD2(s01, a0, a1);
            ADD2(s23, a2, a3);
            ADD2(sall, s01, s23);
            float lo, hi;
            unpack2(sall, lo, hi);
            float s = lo + hi;     // = ||c||^2 - 2*x.c
            if (s < best)       { best2 = best; bestk2 = bestk; best = s; bestk = k0 + kk; }
            else if (s < best2) { best2 = s; bestk2 = k0 + kk; }
        }
    }

    // Rare rescue: near-tie -> reproduce the reference's fp32 rounding exactly,
    // including its lowest-index tie-break.
    if (best2 - best < MARGIN) {
        double A = 0.0;
#pragma unroll
        for (int i = 0; i < D; ++i) A += (double)(x[i] * x[i]);
        float A32 = (float)A;
        int klo = min(bestk, bestk2), khi = max(bestk, bestk2);
        float dlo = ref_score(codebook, klo, x, A32);
        float dhi = ref_score(codebook, khi, x, A32);
        bestk = (dhi < dlo) ? khi : klo;
    }

    atomicAdd(&g_counts[bestk], 1);

    const float4* q = reinterpret_cast<const float4*>(codebook + bestk * D);
    float* outp = out + (b * D) * HWSZ + hw;
#pragma unroll
    for (int i = 0; i < D / 4; ++i) {
        float4 qv = __ldg(&q[i]);
        int c = i * 4;
        outp[(c + 0) * HWSZ] = x[c + 0] + (qv.x - x[c + 0]);
        outp[(c + 1) * HWSZ] = x[c + 1] + (qv.y - x[c + 1]);
        outp[(c + 2) * HWSZ] = x[c + 2] + (qv.z - x[c + 2]);
        outp[(c + 3) * HWSZ] = x[c + 3] + (qv.w - x[c + 3]);
    }
}

// Kernel C: perplexity = exp(-sum(e * log(e + 1e-10))), e = counts / N.
__global__ void vq_perplexity(float* __restrict__ out, int out_size) {
    const int k = threadIdx.x;
    float e = (float)g_counts[k] * (1.0f / (float)NTOK);
    float v = e * logf(e + 1e-10f);
#pragma unroll
    for (int o = 16; o > 0; o >>= 1) v += __shfl_down_sync(0xffffffffu, v, o);
    __shared__ float red[32];
    if ((k & 31) == 0) red[k >> 5] = v;
    __syncthreads();
    if (k < 32) {
        float s = red[k];
#pragma unroll
        for (int o = 16; o > 0; o >>= 1) s += __shfl_down_sync(0xffffffffu, s, o);
        if (k == 0 && out_size > NTOK * D) out[NTOK * D] = expf(-s);
    }
}

extern "C" void kernel_launch(void* const* d_in, const int* in_sizes, int n_in,
                              void* d_out, int out_size) {
    const float* inputs   = (const float*)d_in[0];
    const float* codebook = (const float*)d_in[1];
    float*       out      = (float*)d_out;

    vq_prep<<<(KCODES + 255) / 256, 256>>>(codebook);
    vq_main<<<NTOK / TPB, TPB>>>(inputs, codebook, out);
    vq_perplexity<<<1, KCODES>>>(out, out_size);
}

// round 6
// speedup vs baseline: 2.1967x; 1.7808x over previous
#include <cuda_runtime.h>
#include <cuda_fp16.h>
#include <math.h>

namespace {
constexpr int KCODES = 1024;
constexpr int D      = 64;
constexpr int HWSZ   = 64 * 64;
constexpr int NTOK   = 32 * HWSZ;        // 131072
constexpr int TPB    = 256;              // 8 warps, 16 tokens/warp -> 128 tokens/CTA
constexpr int TOKS   = 128;
constexpr int TILE   = 512;              // codes per smem tile (2 tiles)
constexpr float MARGIN = 0.045f;         // hard bound on 2-sided f16 phase-1 error
constexpr float RESCUE = 1e-4f;          // fp64 grid-rescue threshold (proven R2)

constexpr int ASTRIDE_W = 36;            // A row stride in u32 words (72 halves = 144B)
constexpr int BSTRIDE_W = 36;            // B row stride in u32 words
constexpr int SM_A  = 0;                 // 128 * 144B = 18432
constexpr int SM_B  = 18432;             // 512 * 144B = 73728
constexpr int SM_CN = 92160;             // 1024 f32   = 4096
constexpr int SM_TOTAL = 96256;
}

__device__ float    g_cnorm[KCODES];
__device__ int      g_counts[KCODES];
__device__ unsigned g_cb16[KCODES * 32];   // f16x2 rows of (-2c), plain [code][32 words]

// ---- Kernel A: norms, f16(-2c) rows, zero counts (every launch; replay-safe) ----
__global__ void vq_prep(const float* __restrict__ codebook) {
    int k = blockIdx.x * blockDim.x + threadIdx.x;
    if (k >= KCODES) return;
    const float* row = codebook + k * D;
    float s = 0.f;
#pragma unroll
    for (int j = 0; j < 32; ++j) {
        float a = row[2 * j], b = row[2 * j + 1];
        s = fmaf(a, a, s);
        s = fmaf(b, b, s);
        __half2 h = __floats2half2_rn(-2.0f * a, -2.0f * b);
        g_cb16[k * 32 + j] = *reinterpret_cast<unsigned*>(&h);
    }
    g_cnorm[k] = s;
    g_counts[k] = 0;
}

// Exact emulation of the reference's rounded score (proven in round 2).
__device__ __forceinline__ float ref_score(const float* __restrict__ cb, int k,
                                           const float* x, float A32) {
    const float* cp = cb + k * D;
    double dot = 0.0, C = 0.0;
#pragma unroll
    for (int i = 0; i < D; ++i) {
        float cv = cp[i];
        dot += (double)x[i] * (double)cv;
        C   += (double)(cv * cv);
    }
    float t1 = (float)dot;
    float t2 = A32 - 2.0f * t1;
    return t2 + (float)C;
}

// Exact fp32 rescore, 4-way split (round-2 validated form).
__device__ __forceinline__ float fp32_score(const float* __restrict__ cb, int k,
                                            const float* __restrict__ cn,
                                            const float* x) {
    const float* cp = cb + k * D;
    float d0 = 0.f, d1 = 0.f, d2 = 0.f, d3 = 0.f;
#pragma unroll
    for (int i = 0; i < D / 4; ++i) {
        d0 = fmaf(x[4 * i + 0], __ldg(&cp[4 * i + 0]), d0);
        d1 = fmaf(x[4 * i + 1], __ldg(&cp[4 * i + 1]), d1);
        d2 = fmaf(x[4 * i + 2], __ldg(&cp[4 * i + 2]), d2);
        d3 = fmaf(x[4 * i + 3], __ldg(&cp[4 * i + 3]), d3);
    }
    return cn[k] - 2.0f * ((d0 + d1) + (d2 + d3));
}

__device__ __forceinline__ void ins2(float s, int i, float& b0, int& i0, float& b1, int& i1) {
    if (s < b0 || (s == b0 && i < i0)) { b1 = b0; i1 = i0; b0 = s; i0 = i; }
    else if (s < b1 || (s == b1 && i < i1)) { b1 = s; i1 = i; }
}
__device__ __forceinline__ void butterfly2(float& b0, int& i0, float& b1, int& i1) {
#pragma unroll
    for (int d = 1; d <= 2; d <<= 1) {
        float rb0 = __shfl_xor_sync(0xffffffffu, b0, d);
        float rb1 = __shfl_xor_sync(0xffffffffu, b1, d);
        int   ri0 = __shfl_xor_sync(0xffffffffu, i0, d);
        int   ri1 = __shfl_xor_sync(0xffffffffu, i1, d);
        ins2(rb0, ri0, b0, i0, b1, i1);
        ins2(rb1, ri1, b0, i0, b1, i1);
    }
}

#define HMMA(c0, c1, c2, c3, a0, a1, a2, a3, b0, b1) \
    asm volatile("mma.sync.aligned.m16n8k16.row.col.f32.f16.f16.f32 " \
        "{%0,%1,%2,%3}, {%4,%5,%6,%7}, {%8,%9}, {%0,%1,%2,%3};" \
        : "+f"(c0), "+f"(c1), "+f"(c2), "+f"(c3) \
        : "r"(a0), "r"(a1), "r"(a2), "r"(a3), "r"(b0), "r"(b1))

// ---- Kernel B: HMMA scoring + top-2/rescue ladder + straight-through output ----
__global__ __launch_bounds__(TPB, 2) void vq_main(const float* __restrict__ inputs,
                                                  const float* __restrict__ codebook,
                                                  float* __restrict__ out) {
    extern __shared__ char smem[];
    unsigned* Aw = reinterpret_cast<unsigned*>(smem + SM_A);
    unsigned* Bw = reinterpret_cast<unsigned*>(smem + SM_B);
    float*    cn = reinterpret_cast<float*>(smem + SM_CN);

    const int tid  = threadIdx.x;
    const int wid  = tid >> 5;
    const int lane = tid & 31;
    const int g    = lane >> 2;          // fragment row group 0..7
    const int q    = lane & 3;           // fragment quad 0..3
    const int tok_base = blockIdx.x * TOKS;

    // ---- Stage A (tokens -> f16 smem), cn, B tile 0 ----
    {
        const int tok = tid & 127;
        const int hs  = tid >> 7;                 // which 32-dim half
        const int T   = tok_base + tok;
        const int b   = T >> 12, hw = T & (HWSZ - 1);
        const float* xin = inputs + (b * D + hs * 32) * HWSZ + hw;
        unsigned* dst = Aw + tok * ASTRIDE_W + hs * 16;
#pragma unroll
        for (int j = 0; j < 16; ++j) {
            float v0 = xin[(2 * j) * HWSZ];
            float v1 = xin[(2 * j + 1) * HWSZ];
            __half2 h = __floats2half2_rn(v0, v1);
            dst[j] = *reinterpret_cast<unsigned*>(&h);
        }
        for (int i = tid; i < KCODES; i += TPB) cn[i] = g_cnorm[i];
        const uint4* src = reinterpret_cast<const uint4*>(g_cb16);
        uint4* dstB = reinterpret_cast<uint4*>(smem + SM_B);
        for (int i = tid; i < TILE * 8; i += TPB)
            dstB[(i >> 3) * 9 + (i & 7)] = src[i];
    }
    __syncthreads();

    // ---- Load A fragments (registers, reused for all 1024 codes) ----
    unsigned a[4][4];
    {
        const int rA = (wid * 16 + g) * ASTRIDE_W;
#pragma unroll
        for (int k = 0; k < 4; ++k) {
            a[k][0] = Aw[rA + k * 8 + q];
            a[k][1] = Aw[rA + 8 * ASTRIDE_W + k * 8 + q];
            a[k][2] = Aw[rA + k * 8 + q + 4];
            a[k][3] = Aw[rA + 8 * ASTRIDE_W + k * 8 + q + 4];
        }
    }

    float bA0 = 3.4e38f, bA1 = 3.4e38f, bB0 = 3.4e38f, bB1 = 3.4e38f;
    int   iA0 = 0x7fffffff, iA1 = 0x7fffffff, iB0 = 0x7fffffff, iB1 = 0x7fffffff;

#pragma unroll 1
    for (int tile = 0; tile < 2; ++tile) {
        if (tile == 1) {
            __syncthreads();
            const uint4* src = reinterpret_cast<const uint4*>(g_cb16) + TILE * 8;
            uint4* dstB = reinterpret_cast<uint4*>(smem + SM_B);
            for (int i = tid; i < TILE * 8; i += TPB)
                dstB[(i >> 3) * 9 + (i & 7)] = src[i];
            __syncthreads();
        }
        const int tbase = tile * TILE;
#pragma unroll 2
        for (int ch = 0; ch < TILE / 8; ++ch) {
            const unsigned* bp = Bw + (ch * 8 + g) * BSTRIDE_W + q;
            const int g0 = tbase + ch * 8 + 2 * q;
            float2 cnv = *reinterpret_cast<const float2*>(&cn[g0]);
            float c0 = cnv.x, c1 = cnv.y, c2 = cnv.x, c3 = cnv.y;
#pragma unroll
            for (int k = 0; k < 4; ++k) {
                unsigned b0r = bp[k * 8];
                unsigned b1r = bp[k * 8 + 4];
                HMMA(c0, c1, c2, c3, a[k][0], a[k][1], a[k][2], a[k][3], b0r, b1r);
            }
            if (c0 < bA0) { bA1 = bA0; iA1 = iA0; bA0 = c0; iA0 = g0; }
            else if (c0 < bA1) { bA1 = c0; iA1 = g0; }
            if (c1 < bA0) { bA1 = bA0; iA1 = iA0; bA0 = c1; iA0 = g0 + 1; }
            else if (c1 < bA1) { bA1 = c1; iA1 = g0 + 1; }
            if (c2 < bB0) { bB1 = bB0; iB1 = iB0; bB0 = c2; iB0 = g0; }
            else if (c2 < bB1) { bB1 = c2; iB1 = g0; }
            if (c3 < bB0) { bB1 = bB0; iB1 = iB0; bB0 = c3; iB0 = g0 + 1; }
            else if (c3 < bB1) { bB1 = c3; iB1 = g0 + 1; }
        }
    }

    // ---- Per-row finalize: merge, rescue ladder, histogram, output ----
#pragma unroll 1
    for (int row = 0; row < 2; ++row) {
        const int T  = tok_base + wid * 16 + g + row * 8;
        const int b  = T >> 12, hw = T & (HWSZ - 1);
        float lb0 = row ? bB0 : bA0, lb1 = row ? bB1 : bA1;   // local (disjoint) cands
        int   li0 = row ? iB0 : iA0, li1 = row ? iB1 : iA1;
        float m0 = lb0, m1 = lb1; int j0 = li0, j1 = li1;
        butterfly2(m0, j0, m1, j1);                           // global noisy top-2

        int bestk = j0;
        if (m1 - m0 < MARGIN) {
            // Exact fp32 rescore of this lane's 2 local candidates, then exact merge.
            float xa[D];
            {
                const float* xt = inputs + (b * D) * HWSZ + hw;
#pragma unroll
                for (int i = 0; i < D; ++i) xa[i] = __ldg(&xt[i * HWSZ]);
            }
            float e0 = fp32_score(codebook, li0, cn, xa);
            float e1v = fp32_score(codebook, li1, cn, xa);
            float f0, f1; int k0, k1;
            if (e0 < e1v || (e0 == e1v && li0 < li1)) { f0 = e0; k0 = li0; f1 = e1v; k1 = li1; }
            else                                      { f0 = e1v; k0 = li1; f1 = e0; k1 = li0; }
            butterfly2(f0, k0, f1, k1);                       // exact top-2 of 8 cands
            bestk = k0;
            if (f1 - f0 < RESCUE) {                           // fp64 grid rescue (R2-proven)
                double A = 0.0;
#pragma unroll
                for (int i = 0; i < D; ++i) A += (double)(xa[i] * xa[i]);
                float A32 = (float)A;
                int klo = min(k0, k1), khi = max(k0, k1);
                float dlo = ref_score(codebook, klo, xa, A32);
                float dhi = ref_score(codebook, khi, xa, A32);
                bestk = (dhi < dlo) ? khi : klo;
            }
        }

        if (q == 0) atomicAdd(&g_counts[bestk], 1);

        // Straight-through output: lane q handles dims q*16 .. q*16+15.
        const float* xt = inputs + (b * D) * HWSZ + hw;
        const float* qp = codebook + bestk * D;
        float* op = out + (b * D) * HWSZ + hw;
#pragma unroll
        for (int m = 0; m < 16; ++m) {
            int c = q * 16 + m;
            float xv = __ldg(&xt[c * HWSZ]);
            op[c * HWSZ] = xv + (__ldg(&qp[c]) - xv);
        }
    }
}

// ---- Kernel C: perplexity ----
__global__ void vq_perplexity(float* __restrict__ out, int out_size) {
    const int k = threadIdx.x;
    float e = (float)g_counts[k] * (1.0f / (float)NTOK);
    float v = e * logf(e + 1e-10f);
#pragma unroll
    for (int o = 16; o > 0; o >>= 1) v += __shfl_down_sync(0xffffffffu, v, o);
    __shared__ float red[32];
    if ((k & 31) == 0) red[k >> 5] = v;
    __syncthreads();
    if (k < 32) {
        float s = red[k];
#pragma unroll
        for (int o = 16; o > 0; o >>= 1) s += __shfl_down_sync(0xffffffffu, s, o);
        if (k == 0 && out_size > NTOK * D) out[NTOK * D] = expf(-s);
    }
}

extern "C" void kernel_launch(void* const* d_in, const int* in_sizes, int n_in,
                              void* d_out, int out_size) {
    const float* inputs   = (const float*)d_in[0];
    const float* codebook = (const float*)d_in[1];
    float*       out      = (float*)d_out;

    cudaFuncSetAttribute(vq_main, cudaFuncAttributeMaxDynamicSharedMemorySize, SM_TOTAL);

    vq_prep<<<(KCODES + 255) / 256, 256>>>(codebook);
    vq_main<<<NTOK / TOKS, TPB, SM_TOTAL>>>(inputs, codebook, out);
    vq_perplexity<<<1, KCODES>>>(out, out_size);
}

// round 7
// speedup vs baseline: 3.5942x; 1.6362x over previous
#include <cuda_runtime.h>
#include <cuda_fp16.h>
#include <math.h>

namespace {
constexpr int KCODES = 1024;
constexpr int D      = 64;
constexpr int HWSZ   = 64 * 64;
constexpr int NTOK   = 32 * HWSZ;        // 131072
constexpr int TPB    = 256;              // 8 warps, 128 tokens/CTA
constexpr int TOKS   = 128;
constexpr int TILE   = 512;              // codes per smem tile (2 tiles)
constexpr float MARGIN = 0.045f;         // hard 2-sided f16 phase-1 error bound (R6-proven)
constexpr float RESCUE = 1e-4f;          // fp64 grid-rescue threshold (R2-proven)

constexpr int ASTRIDE_W = 36;            // A row stride in u32 words (144B)
constexpr int BSTRIDE_W = 36;
constexpr int SM_A  = 0;                 // 128 * 144B
constexpr int SM_B  = 18432;             // 512 * 144B
constexpr int SM_CN = 92160;             // 1024 f32
constexpr int SM_TOTAL = 96256;
}

__device__ float    g_cnorm[KCODES];
__device__ int      g_counts[KCODES];
__device__ unsigned g_cb16[KCODES * 32];   // f16x2 rows of (-2c)
__device__ int      g_nflag;
__device__ int      g_ftok[NTOK];
__device__ uint4    g_fcand[NTOK];         // 8 candidate ids as 4x(u16,u16)

// ---- Kernel A: warp-per-code prep (norms, f16(-2c), zero counts/worklist) ----
__global__ void vq_prep(const float* __restrict__ codebook) {
    const int w    = (blockIdx.x * blockDim.x + threadIdx.x) >> 5;   // code id
    const int lane = threadIdx.x & 31;
    if (w >= KCODES) return;
    float a = codebook[w * D + 2 * lane];
    float b = codebook[w * D + 2 * lane + 1];
    __half2 h = __floats2half2_rn(-2.0f * a, -2.0f * b);
    g_cb16[w * 32 + lane] = *reinterpret_cast<unsigned*>(&h);
    float p = fmaf(a, a, b * b);
#pragma unroll
    for (int o = 16; o > 0; o >>= 1) p += __shfl_xor_sync(0xffffffffu, p, o);
    if (lane == 0) { g_cnorm[w] = p; g_counts[w] = 0; }
    if (blockIdx.x == 0 && threadIdx.x == 0) g_nflag = 0;
}

// Exact emulation of the reference's rounded score (proven in round 2).
__device__ __forceinline__ float ref_score(const float* __restrict__ cb, int k,
                                           const float* x, float A32) {
    const float* cp = cb + k * D;
    double dot = 0.0, C = 0.0;
#pragma unroll
    for (int i = 0; i < D; ++i) {
        float cv = cp[i];
        dot += (double)x[i] * (double)cv;
        C   += (double)(cv * cv);
    }
    float t1 = (float)dot;
    float t2 = A32 - 2.0f * t1;
    return t2 + (float)C;
}

__device__ __forceinline__ float fp32_score(const float* __restrict__ cb, int k,
                                            const float* x) {
    const float* cp = cb + k * D;
    float d0 = 0.f, d1 = 0.f, d2 = 0.f, d3 = 0.f;
#pragma unroll
    for (int i = 0; i < D / 4; ++i) {
        d0 = fmaf(x[4 * i + 0], __ldg(&cp[4 * i + 0]), d0);
        d1 = fmaf(x[4 * i + 1], __ldg(&cp[4 * i + 1]), d1);
        d2 = fmaf(x[4 * i + 2], __ldg(&cp[4 * i + 2]), d2);
        d3 = fmaf(x[4 * i + 3], __ldg(&cp[4 * i + 3]), d3);
    }
    return g_cnorm[k] - 2.0f * ((d0 + d1) + (d2 + d3));
}

__device__ __forceinline__ void ins2(float s, int i, float& b0, int& i0, float& b1, int& i1) {
    if (s < b0 || (s == b0 && i < i0)) { b1 = b0; i1 = i0; b0 = s; i0 = i; }
    else if (s < b1 || (s == b1 && i < i1)) { b1 = s; i1 = i; }
}
__device__ __forceinline__ void butterfly2(float& b0, int& i0, float& b1, int& i1) {
#pragma unroll
    for (int d = 1; d <= 2; d <<= 1) {
        float rb0 = __shfl_xor_sync(0xffffffffu, b0, d);
        float rb1 = __shfl_xor_sync(0xffffffffu, b1, d);
        int   ri0 = __shfl_xor_sync(0xffffffffu, i0, d);
        int   ri1 = __shfl_xor_sync(0xffffffffu, i1, d);
        ins2(rb0, ri0, b0, i0, b1, i1);
        ins2(rb1, ri1, b0, i0, b1, i1);
    }
}

#define HMMA(c0, c1, c2, c3, a0, a1, a2, a3, b0, b1) \
    asm volatile("mma.sync.aligned.m16n8k16.row.col.f32.f16.f16.f32 " \
        "{%0,%1,%2,%3}, {%4,%5,%6,%7}, {%8,%9}, {%0,%1,%2,%3};" \
        : "+f"(c0), "+f"(c1), "+f"(c2), "+f"(c3) \
        : "r"(a0), "r"(a1), "r"(a2), "r"(a3), "r"(b0), "r"(b1))

// ---- Kernel B: HMMA scoring + noisy top-2; flagged quads -> worklist ----
__global__ __launch_bounds__(TPB, 2) void vq_main(const float* __restrict__ inputs,
                                                  const float* __restrict__ codebook,
                                                  float* __restrict__ out) {
    extern __shared__ char smem[];
    unsigned* Aw = reinterpret_cast<unsigned*>(smem + SM_A);
    unsigned* Bw = reinterpret_cast<unsigned*>(smem + SM_B);
    float*    cn = reinterpret_cast<float*>(smem + SM_CN);

    const int tid  = threadIdx.x;
    const int wid  = tid >> 5;
    const int lane = tid & 31;
    const int g    = lane >> 2;
    const int q    = lane & 3;
    const int tok_base = blockIdx.x * TOKS;

    // Stage A (tokens -> f16 smem), cn, B tile 0.
    {
        const int tok = tid & 127;
        const int hs  = tid >> 7;
        const int T   = tok_base + tok;
        const int b   = T >> 12, hw = T & (HWSZ - 1);
        const float* xin = inputs + (b * D + hs * 32) * HWSZ + hw;
        unsigned* dst = Aw + tok * ASTRIDE_W + hs * 16;
#pragma unroll
        for (int j = 0; j < 16; ++j) {
            __half2 h = __floats2half2_rn(xin[(2 * j) * HWSZ], xin[(2 * j + 1) * HWSZ]);
            dst[j] = *reinterpret_cast<unsigned*>(&h);
        }
        for (int i = tid; i < KCODES; i += TPB) cn[i] = g_cnorm[i];
        const uint4* src = reinterpret_cast<const uint4*>(g_cb16);
        uint4* dstB = reinterpret_cast<uint4*>(smem + SM_B);
        for (int i = tid; i < TILE * 8; i += TPB)
            dstB[(i >> 3) * 9 + (i & 7)] = src[i];
    }
    __syncthreads();

    unsigned a[4][4];
    {
        const int rA = (wid * 16 + g) * ASTRIDE_W;
#pragma unroll
        for (int k = 0; k < 4; ++k) {
            a[k][0] = Aw[rA + k * 8 + q];
            a[k][1] = Aw[rA + 8 * ASTRIDE_W + k * 8 + q];
            a[k][2] = Aw[rA + k * 8 + q + 4];
            a[k][3] = Aw[rA + 8 * ASTRIDE_W + k * 8 + q + 4];
        }
    }

    float bA0 = 3.4e38f, bA1 = 3.4e38f, bB0 = 3.4e38f, bB1 = 3.4e38f;
    int   iA0 = 0x7fffffff, iA1 = 0x7fffffff, iB0 = 0x7fffffff, iB1 = 0x7fffffff;

#pragma unroll 1
    for (int tile = 0; tile < 2; ++tile) {
        if (tile == 1) {
            __syncthreads();
            const uint4* src = reinterpret_cast<const uint4*>(g_cb16) + TILE * 8;
            uint4* dstB = reinterpret_cast<uint4*>(smem + SM_B);
            for (int i = tid; i < TILE * 8; i += TPB)
                dstB[(i >> 3) * 9 + (i & 7)] = src[i];
            __syncthreads();
        }
        const int tbase = tile * TILE;
#pragma unroll 4
        for (int ch = 0; ch < TILE / 8; ++ch) {
            const unsigned* bp = Bw + (ch * 8 + g) * BSTRIDE_W + q;
            const int g0 = tbase + ch * 8 + 2 * q;
            float2 cnv = *reinterpret_cast<const float2*>(&cn[g0]);
            float c0 = cnv.x, c1 = cnv.y, c2 = cnv.x, c3 = cnv.y;
#pragma unroll
            for (int k = 0; k < 4; ++k)
                HMMA(c0, c1, c2, c3, a[k][0], a[k][1], a[k][2], a[k][3],
                     bp[k * 8], bp[k * 8 + 4]);
            if (c0 < bA0) { bA1 = bA0; iA1 = iA0; bA0 = c0; iA0 = g0; }
            else if (c0 < bA1) { bA1 = c0; iA1 = g0; }
            if (c1 < bA0) { bA1 = bA0; iA1 = iA0; bA0 = c1; iA0 = g0 + 1; }
            else if (c1 < bA1) { bA1 = c1; iA1 = g0 + 1; }
            if (c2 < bB0) { bB1 = bB0; iB1 = iB0; bB0 = c2; iB0 = g0; }
            else if (c2 < bB1) { bB1 = c2; iB1 = g0; }
            if (c3 < bB0) { bB1 = bB0; iB1 = iB0; bB0 = c3; iB0 = g0 + 1; }
            else if (c3 < bB1) { bB1 = c3; iB1 = g0 + 1; }
        }
    }

#pragma unroll 1
    for (int row = 0; row < 2; ++row) {
        const int T  = tok_base + wid * 16 + g + row * 8;
        const int b  = T >> 12, hw = T & (HWSZ - 1);
        float lb0 = row ? bB0 : bA0, lb1 = row ? bB1 : bA1;
        int   li0 = row ? iB0 : iA0, li1 = row ? iB1 : iA1;
        float m0 = lb0, m1 = lb1; int j0 = li0, j1 = li1;
        butterfly2(m0, j0, m1, j1);                  // quad-level noisy top-2

        // Gather the quad's 8 local candidates (full-warp shuffles, no divergence).
        unsigned myc = (unsigned)li0 | ((unsigned)li1 << 16);
        unsigned qb  = lane & ~3u;
        unsigned c0w = __shfl_sync(0xffffffffu, myc, qb + 0);
        unsigned c1w = __shfl_sync(0xffffffffu, myc, qb + 1);
        unsigned c2w = __shfl_sync(0xffffffffu, myc, qb + 2);
        unsigned c3w = __shfl_sync(0xffffffffu, myc, qb + 3);

        if (m1 - m0 < MARGIN) {                      // flagged -> defer to rescue kernel
            if (q == 0) {
                int wv = atomicAdd(&g_nflag, 1);
                g_ftok[wv]  = T;
                g_fcand[wv] = make_uint4(c0w, c1w, c2w, c3w);
            }
        } else {                                     // safe: noisy winner is exact
            const int bestk = j0;
            if (q == 0) atomicAdd(&g_counts[bestk], 1);
            const float* xt = inputs + (b * D) * HWSZ + hw;
            const float* qp = codebook + bestk * D;
            float* op = out + (b * D) * HWSZ + hw;
#pragma unroll
            for (int m = 0; m < 16; ++m) {
                int c = q * 16 + m;
                float xv = __ldg(&xt[c * HWSZ]);
                op[c * HWSZ] = xv + (__ldg(&qp[c]) - xv);
            }
        }
    }
}

// ---- Kernel C: exact rescue for flagged tokens (identical ladder to round 6) ----
__global__ void vq_rescue(const float* __restrict__ inputs,
                          const float* __restrict__ codebook,
                          float* __restrict__ out) {
    const int n = g_nflag;
    for (int i = blockIdx.x * blockDim.x + threadIdx.x; i < n;
         i += gridDim.x * blockDim.x) {
        const int T = g_ftok[i];
        const uint4 cw = g_fcand[i];
        int cand[8] = { (int)(cw.x & 0xffff), (int)(cw.x >> 16),
                        (int)(cw.y & 0xffff), (int)(cw.y >> 16),
                        (int)(cw.z & 0xffff), (int)(cw.z >> 16),
                        (int)(cw.w & 0xffff), (int)(cw.w >> 16) };
        const int b = T >> 12, hw = T & (HWSZ - 1);
        const float* xt = inputs + (b * D) * HWSZ + hw;
        float xa[D];
#pragma unroll
        for (int d2 = 0; d2 < D; ++d2) xa[d2] = __ldg(&xt[d2 * HWSZ]);

        float e0 = 3.4e38f, e1 = 3.4e38f;
        int   k0 = 0x7fffffff, k1 = 0x7fffffff;
#pragma unroll
        for (int j = 0; j < 8; ++j) {
            int k = cand[j];
            float e = fp32_score(codebook, k, xa);
            if (e < e0 || (e == e0 && k < k0)) { e1 = e0; k1 = k0; e0 = e; k0 = k; }
            else if (e < e1 || (e == e1 && k < k1)) { e1 = e; k1 = k; }
        }
        int bestk = k0;
        if (e1 - e0 < RESCUE) {                      // fp64 grid rescue (R2-proven)
            double A = 0.0;
#pragma unroll
            for (int d2 = 0; d2 < D; ++d2) A += (double)(xa[d2] * xa[d2]);
            float A32 = (float)A;
            int klo = min(k0, k1), khi = max(k0, k1);
            float dlo = ref_score(codebook, klo, xa, A32);
            float dhi = ref_score(codebook, khi, xa, A32);
            bestk = (dhi < dlo) ? khi : klo;
        }
        atomicAdd(&g_counts[bestk], 1);
        const float* qp = codebook + bestk * D;
        float* op = out + (b * D) * HWSZ + hw;
#pragma unroll
        for (int c = 0; c < D; ++c) {
            float xv = xa[c];
            op[c * HWSZ] = xv + (__ldg(&qp[c]) - xv);
        }
    }
}

// ---- Kernel D: perplexity ----
__global__ void vq_perplexity(float* __restrict__ out, int out_size) {
    const int k = threadIdx.x;
    float e = (float)g_counts[k] * (1.0f / (float)NTOK);
    float v = e * logf(e + 1e-10f);
#pragma unroll
    for (int o = 16; o > 0; o >>= 1) v += __shfl_down_sync(0xffffffffu, v, o);
    __shared__ float red[32];
    if ((k & 31) == 0) red[k >> 5] = v;
    __syncthreads();
    if (k < 32) {
        float s = red[k];
#pragma unroll
        for (int o = 16; o > 0; o >>= 1) s += __shfl_down_sync(0xffffffffu, s, o);
        if (k == 0 && out_size > NTOK * D) out[NTOK * D] = expf(-s);
    }
}

extern "C" void kernel_launch(void* const* d_in, const int* in_sizes, int n_in,
                              void* d_out, int out_size) {
    const float* inputs   = (const float*)d_in[0];
    const float* codebook = (const float*)d_in[1];
    float*       out      = (float*)d_out;

    cudaFuncSetAttribute(vq_main, cudaFuncAttributeMaxDynamicSharedMemorySize, SM_TOTAL);

    vq_prep<<<KCODES / 8, TPB>>>(codebook);
    vq_main<<<NTOK / TOKS, TPB, SM_TOTAL>>>(inputs, codebook, out);
    vq_rescue<<<256, 128>>>(inputs, codebook, out);
    vq_perplexity<<<1, KCODES>>>(out, out_size);
}